// round 16
// baseline (speedup 1.0000x reference)
#include <cuda_runtime.h>
#include <cuda_fp16.h>
#include <math.h>
#include <stdint.h>

// ---------------------------------------------------------------------------
// Problem constants
// ---------------------------------------------------------------------------
#define HID   1024
#define NHEAD 16
#define HD    64
#define INTER 4096
#define BATCH 4
#define SEQ   2048
#define NTOK  (BATCH * SEQ)          // 8192
#define LN_EPS 1e-5f

// ---------------------------------------------------------------------------
// Scratch (static device globals; no runtime allocation)
// mma path single fp16; residual-1 now fp16 as well.
// ---------------------------------------------------------------------------
__device__ __half g_x1 [NTOK * HID];             // residual-1 (fp16)
__device__ __half g_qkv[NTOK * 3 * HID];         // QKV
__device__ __half g_h   [NTOK * HID];            // LN out
__device__ __half g_attn[NTOK * HID];            // attention out
__device__ __half g_mid [NTOK * INTER];          // GELU(MLP1)
__device__ __half g_wqkv[HID * 3 * HID];         // fp16 weights
__device__ __half g_wout[HID * HID];
__device__ __half g_w1  [HID * INTER];
__device__ __half g_w2  [INTER * HID];

// ---------------------------------------------------------------------------
// PTX helpers (sm_80-baseline features only)
// ---------------------------------------------------------------------------
__device__ __forceinline__ uint32_t smem_u32(const void* p) {
    uint32_t a;
    asm("{ .reg .u64 t; cvta.to.shared.u64 t, %1; cvt.u32.u64 %0, t; }"
        : "=r"(a) : "l"(p));
    return a;
}
__device__ __forceinline__ void ldsm4(uint32_t* r, uint32_t addr) {
    asm volatile("ldmatrix.sync.aligned.m8n8.x4.shared.b16 {%0,%1,%2,%3}, [%4];"
                 : "=r"(r[0]), "=r"(r[1]), "=r"(r[2]), "=r"(r[3]) : "r"(addr));
}
__device__ __forceinline__ void ldsm4t(uint32_t* r, uint32_t addr) {
    asm volatile("ldmatrix.sync.aligned.m8n8.x4.trans.shared.b16 {%0,%1,%2,%3}, [%4];"
                 : "=r"(r[0]), "=r"(r[1]), "=r"(r[2]), "=r"(r[3]) : "r"(addr));
}
__device__ __forceinline__ void mma_f16(float* c, const uint32_t* a,
                                        uint32_t b0, uint32_t b1) {
    asm volatile(
        "mma.sync.aligned.m16n8k16.row.col.f32.f16.f16.f32 "
        "{%0,%1,%2,%3}, {%4,%5,%6,%7}, {%8,%9}, {%0,%1,%2,%3};"
        : "+f"(c[0]), "+f"(c[1]), "+f"(c[2]), "+f"(c[3])
        : "r"(a[0]), "r"(a[1]), "r"(a[2]), "r"(a[3]), "r"(b0), "r"(b1));
}
__device__ __forceinline__ void cpasync16(uint32_t s, const void* g) {
    asm volatile("cp.async.cg.shared.global [%0], [%1], 16;" :: "r"(s), "l"(g));
}
#define CP_COMMIT() asm volatile("cp.async.commit_group;" ::: "memory")
#define CP_WAIT1()  asm volatile("cp.async.wait_group 1;"  ::: "memory")
#define CP_WAIT0()  asm volatile("cp.async.wait_group 0;"  ::: "memory")

__device__ __forceinline__ uint32_t swB(uint32_t off) { return off ^ ((off >> 4) & 0x70); }
__device__ __forceinline__ uint32_t sw128(uint32_t off) { return off ^ ((off >> 3) & 0x70); }

__device__ __forceinline__ uint32_t pack_h2(float x, float y) {
    __half2 h = __floats2half2_rn(x, y);
    return *(uint32_t*)&h;
}

// ---------------------------------------------------------------------------
// Weight fp32 -> fp16
// ---------------------------------------------------------------------------
__global__ __launch_bounds__(256) void convw(
    const float* __restrict__ w, __half* __restrict__ hi, int n)
{
    const int i = (blockIdx.x * 256 + threadIdx.x) * 4;
    if (i >= n) return;
    const float4 v = *(const float4*)(w + i);
    __half2 h01 = __floats2half2_rn(v.x, v.y);
    __half2 h23 = __floats2half2_rn(v.z, v.w);
    uint2 hv;
    hv.x = *(uint32_t*)&h01; hv.y = *(uint32_t*)&h23;
    *(uint2*)(hi + i) = hv;
}

// ---------------------------------------------------------------------------
// fp16 HMMA GEMM: C = A @ B + bias (+epilogue).
// Tile 128x128, BK=64, cp.async 3-stage (32KB/stage = 96KB smem, 2 CTA/SM).
// Stage: A [128 rows x 128B, sw128] | B [64 rows x 256B, swB] at +16384.
// EPI: 0 = +bias -> fp16; 1 = +bias + fp32 res -> fp16 (proj -> x1);
//      2 = +bias+GELU -> fp16; 3 = +bias + fp16 res -> fp32 (MLP2 -> out)
// ---------------------------------------------------------------------------
#define BM 128
#define BN 128
#define BK 64
#define ST_BYTES 32768
#define HG2_SMEM (3 * ST_BYTES)

template <int EPI>
__global__ __launch_bounds__(256, 2) void hgemm2(
    const __half* __restrict__ A, const __half* __restrict__ B,
    const float* __restrict__ bias, const float* __restrict__ resF,
    const __half* __restrict__ resH,
    float* __restrict__ Cf, __half* __restrict__ Ch,
    int M, int N, int K)
{
    extern __shared__ char smem[];
    const uint32_t sb = smem_u32(smem);
    const int tid  = threadIdx.x;
    const int lane = tid & 31;
    const int wid  = tid >> 5;
    const int m0   = blockIdx.y * BM;
    const int n0   = blockIdx.x * BN;

    // A loader: 2 threads/row, 32 elems (64B) each -> 4 x 16B
    const int ar = tid >> 1;
    const int ac = (tid & 1) * 32;
    // B loader: 4 threads/row (64 rows x 256B), 32 elems each -> 4 x 16B
    const int br = tid >> 2;
    const int bc = (tid & 3) * 32;
    uint32_t sA[4], sBo[4];
    #pragma unroll
    for (int i = 0; i < 4; i++) {
        sA[i]  = sw128(ar * 128 + (ac + i * 8) * 2);
        sBo[i] = swB(br * 256 + (bc + i * 8) * 2) + 16384;
    }
    const size_t aoff = (size_t)(m0 + ar) * K + ac;

    auto PRE = [&](int c, int s) {
        const uint32_t st = sb + s * ST_BYTES;
        const __half* ap = A + aoff + c * BK;
        const __half* bp = B + (size_t)(c * BK + br) * N + n0 + bc;
        #pragma unroll
        for (int i = 0; i < 4; i++) cpasync16(st + sA[i], ap + i * 8);
        #pragma unroll
        for (int i = 0; i < 4; i++) cpasync16(st + sBo[i], bp + i * 8);
    };

    const int wm  = (wid & 3) * 32;
    const int wn  = (wid >> 2) * 64;
    const int a_r = lane & 15;
    const int a_k = (lane >> 4) * 8;
    const int b_k = lane & 15;
    const int b_n = (lane >> 4) * 8;

    float acc[2][8][4];
    #pragma unroll
    for (int i = 0; i < 2; i++)
        #pragma unroll
        for (int j = 0; j < 8; j++)
            #pragma unroll
            for (int q = 0; q < 4; q++) acc[i][j][q] = 0.f;

    auto COMPUTE = [&](int s) {
        const uint32_t AS = sb + s * ST_BYTES;
        const uint32_t BS = AS + 16384;
        #pragma unroll
        for (int ks = 0; ks < 4; ks++) {
            uint32_t a_[2][4];
            #pragma unroll
            for (int mt = 0; mt < 2; mt++) {
                const uint32_t off =
                    sw128((wm + mt * 16 + a_r) * 128 + (ks * 16 + a_k) * 2);
                ldsm4(a_[mt], AS + off);
            }
            #pragma unroll
            for (int ng = 0; ng < 4; ng++) {
                uint32_t bh[4];
                const uint32_t off =
                    swB((ks * 16 + b_k) * 256 + (wn + ng * 16 + b_n) * 2);
                ldsm4t(bh, BS + off);
                #pragma unroll
                for (int mt = 0; mt < 2; mt++) {
                    #pragma unroll
                    for (int hf = 0; hf < 2; hf++)
                        mma_f16(acc[mt][ng * 2 + hf], a_[mt],
                                bh[hf * 2], bh[hf * 2 + 1]);
                }
            }
        }
    };

    PRE(0, 0); CP_COMMIT();
    PRE(1, 1); CP_COMMIT();
    const int NC = K / BK;
    #pragma unroll 1
    for (int c = 0; c < NC; c++) {
        const int s = c - (c / 3) * 3;
        CP_WAIT1();
        __syncthreads();
        COMPUTE(s);
        if (c + 2 < NC) {
            const int s2 = (c + 2) - ((c + 2) / 3) * 3;
            PRE(c + 2, s2);
        }
        CP_COMMIT();
    }

    #pragma unroll
    for (int mt = 0; mt < 2; mt++) {
        #pragma unroll
        for (int nt = 0; nt < 8; nt++) {
            const int r0 = m0 + wm + mt * 16 + (lane >> 2);
            const int cc = n0 + wn + nt * 8 + (lane & 3) * 2;
            const float bx = bias[cc], by = bias[cc + 1];
            #pragma unroll
            for (int half = 0; half < 2; half++) {
                const int r = r0 + half * 8;
                float vx = acc[mt][nt][half * 2 + 0] + bx;
                float vy = acc[mt][nt][half * 2 + 1] + by;
                if (EPI == 2) {
                    float t = tanhf(0.7978845608028654f * (vx + 0.044715f * vx * vx * vx));
                    vx = 0.5f * vx * (1.0f + t);
                    t = tanhf(0.7978845608028654f * (vy + 0.044715f * vy * vy * vy));
                    vy = 0.5f * vy * (1.0f + t);
                }
                if (EPI == 1) {
                    const float2 rv = *(const float2*)(resF + (size_t)r * N + cc);
                    vx += rv.x; vy += rv.y;
                }
                if (EPI == 3) {
                    const __half2 rh = *(const __half2*)(resH + (size_t)r * N + cc);
                    vx += __low2float(rh); vy += __high2float(rh);
                    float2 w; w.x = vx; w.y = vy;
                    *(float2*)(Cf + (size_t)r * N + cc) = w;
                } else {
                    *(__half2*)(Ch + (size_t)r * N + cc) = __floats2half2_rn(vx, vy);
                }
            }
        }
    }
}

// ---------------------------------------------------------------------------
// Tensor-core flash attention (unchanged from R15): single fp16, 1-term.
// One CTA = 128 q-rows x (head,batch); 8 warps; KV chunks of 64,
// 2-stage cp.async. Smem: Q 16K | 2 x (K 8K + V 8K) = 48KB.
// ---------------------------------------------------------------------------
#define QT 128
#define KT 64
#define ATT_SMEM (16384 + 2 * 16384)

__global__ __launch_bounds__(256, 2) void attn_mma()
{
    extern __shared__ char smem[];
    const uint32_t sb = smem_u32(smem);
    const int tid  = threadIdx.x;
    const int lane = tid & 31;
    const int wid  = tid >> 5;
    const int h    = blockIdx.y;
    const int bb   = blockIdx.z;
    const int q0   = blockIdx.x * QT;

    {
        const int qr  = tid >> 1;
        const int qc0 = (tid & 1) * 32;
        const size_t gq = (size_t)(bb * SEQ + q0 + qr) * 3072 + h * 64 + qc0;
        #pragma unroll
        for (int i = 0; i < 4; i++) {
            const uint32_t so = sw128(qr * 128 + (qc0 + i * 8) * 2);
            cpasync16(sb + so, g_qkv + gq + i * 8);
        }
    }

    const int kr = tid >> 2;
    const int kc = (tid & 3) * 16;
    auto PRE = [&](int c, int s) {
        const uint32_t st = sb + 16384 + s * 16384;
        const size_t base = (size_t)(bb * SEQ + c * KT + kr) * 3072 + h * 64 + kc;
        const uint32_t so0 = sw128(kr * 128 + kc * 2);
        const uint32_t so1 = so0 ^ 16;
        cpasync16(st + so0,         g_qkv + base + 1024);
        cpasync16(st + so1,         g_qkv + base + 1024 + 8);
        cpasync16(st + 8192 + so0,  g_qkv + base + 2048);
        cpasync16(st + 8192 + so1,  g_qkv + base + 2048 + 8);
    };

    PRE(0, 0); CP_COMMIT();
    PRE(1, 1); CP_COMMIT();
    CP_WAIT1();
    __syncthreads();

    const int wm = wid * 16;

    float oacc[8][4];
    #pragma unroll
    for (int j = 0; j < 8; j++)
        #pragma unroll
        for (int q = 0; q < 4; q++) oacc[j][q] = 0.f;
    float m0 = -1e30f, m1 = -1e30f, l0 = 0.f, l1 = 0.f;

    const int k_rowadd = ((lane >> 4) & 1) * 8;
    const int k_koff   = ((lane >> 3) & 1) * 8;
    const int k_r8     = lane & 7;

    const int NCH = SEQ / KT;
    #pragma unroll 1
    for (int c = 0; c < NCH; c++) {
        const int s = c & 1;
        const uint32_t st  = sb + 16384 + s * 16384;
        const uint32_t Kb = st, Vb = st + 8192;

        float sacc[8][4];
        #pragma unroll
        for (int j = 0; j < 8; j++)
            #pragma unroll
            for (int q = 0; q < 4; q++) sacc[j][q] = 0.f;

        #pragma unroll
        for (int ks = 0; ks < 4; ks++) {
            uint32_t qf[4];
            const uint32_t qoff =
                sw128((wm + (lane & 15)) * 128 + (ks * 16 + (lane >> 4) * 8) * 2);
            ldsm4(qf, sb + qoff);
            #pragma unroll
            for (int j = 0; j < 4; j++) {
                const uint32_t off = sw128((j * 16 + k_r8 + k_rowadd) * 128 +
                                           (ks * 16 + k_koff) * 2);
                uint32_t kb[4];
                ldsm4(kb, Kb + off);
                #pragma unroll
                for (int t2 = 0; t2 < 2; t2++)
                    mma_f16(sacc[j * 2 + t2], qf, kb[t2 * 2], kb[t2 * 2 + 1]);
            }
        }

        float vm0 = -1e30f, vm1 = -1e30f;
        #pragma unroll
        for (int j = 0; j < 8; j++) {
            vm0 = fmaxf(vm0, fmaxf(sacc[j][0], sacc[j][1]));
            vm1 = fmaxf(vm1, fmaxf(sacc[j][2], sacc[j][3]));
        }
        vm0 = fmaxf(vm0, __shfl_xor_sync(0xffffffffu, vm0, 1));
        vm0 = fmaxf(vm0, __shfl_xor_sync(0xffffffffu, vm0, 2));
        vm1 = fmaxf(vm1, __shfl_xor_sync(0xffffffffu, vm1, 1));
        vm1 = fmaxf(vm1, __shfl_xor_sync(0xffffffffu, vm1, 2));
        vm0 *= 0.125f; vm1 *= 0.125f;

        const float mn0 = fmaxf(m0, vm0), mn1 = fmaxf(m1, vm1);
        const float c0 = __expf(m0 - mn0), c1 = __expf(m1 - mn1);
        m0 = mn0; m1 = mn1;
        l0 *= c0;  l1 *= c1;
        #pragma unroll
        for (int j = 0; j < 8; j++) {
            oacc[j][0] *= c0; oacc[j][1] *= c0;
            oacc[j][2] *= c1; oacc[j][3] *= c1;
        }
        #pragma unroll
        for (int j = 0; j < 8; j++) {
            sacc[j][0] = __expf(fmaf(sacc[j][0], 0.125f, -mn0));
            sacc[j][1] = __expf(fmaf(sacc[j][1], 0.125f, -mn0));
            sacc[j][2] = __expf(fmaf(sacc[j][2], 0.125f, -mn1));
            sacc[j][3] = __expf(fmaf(sacc[j][3], 0.125f, -mn1));
            l0 += sacc[j][0] + sacc[j][1];
            l1 += sacc[j][2] + sacc[j][3];
        }

        #pragma unroll
        for (int kk = 0; kk < 4; kk++) {
            const float* p0 = sacc[kk * 2];
            const float* p1 = sacc[kk * 2 + 1];
            uint32_t pa[4];
            pa[0] = pack_h2(p0[0], p0[1]);
            pa[1] = pack_h2(p0[2], p0[3]);
            pa[2] = pack_h2(p1[0], p1[1]);
            pa[3] = pack_h2(p1[2], p1[3]);
            #pragma unroll
            for (int j = 0; j < 4; j++) {
                const uint32_t off = sw128((kk * 16 + (lane & 15)) * 128 +
                                           (j * 16 + (lane >> 4) * 8) * 2);
                uint32_t vb[4];
                ldsm4t(vb, Vb + off);
                #pragma unroll
                for (int t2 = 0; t2 < 2; t2++)
                    mma_f16(oacc[j * 2 + t2], pa, vb[t2 * 2], vb[t2 * 2 + 1]);
            }
        }

        if (c + 1 < NCH) {
            __syncthreads();
            if (c + 2 < NCH) {
                PRE(c + 2, s);
                CP_COMMIT();
                CP_WAIT1();
            } else {
                CP_WAIT0();
            }
            __syncthreads();
        }
    }

    l0 += __shfl_xor_sync(0xffffffffu, l0, 1);
    l0 += __shfl_xor_sync(0xffffffffu, l0, 2);
    l1 += __shfl_xor_sync(0xffffffffu, l1, 1);
    l1 += __shfl_xor_sync(0xffffffffu, l1, 2);
    const float i0 = 1.f / l0, i1 = 1.f / l1;

    const int r0g = bb * SEQ + q0 + wm + (lane >> 2);
    const int cb  = h * 64 + (lane & 3) * 2;
    #pragma unroll
    for (int j = 0; j < 8; j++) {
        *(__half2*)(g_attn + (size_t)r0g * HID + cb + j * 8) =
            __floats2half2_rn(oacc[j][0] * i0, oacc[j][1] * i0);
        *(__half2*)(g_attn + (size_t)(r0g + 8) * HID + cb + j * 8) =
            __floats2half2_rn(oacc[j][2] * i1, oacc[j][3] * i1);
    }
}

// ---------------------------------------------------------------------------
// LayerNorm: FP16IN=0 -> fp32 input; FP16IN=1 -> fp16 input. fp16 out.
// ---------------------------------------------------------------------------
template <int FP16IN>
__global__ __launch_bounds__(256) void ln_kernel(
    const void* __restrict__ Xv, const float* __restrict__ g,
    const float* __restrict__ b, __half* __restrict__ Y)
{
    __shared__ float red[16];
    const long row = blockIdx.x;
    const int  t   = threadIdx.x;

    float x0, x1v, x2, x3;
    if (FP16IN) {
        const uint2 u = ((const uint2*)((const __half*)Xv + row * HID))[t];
        const __half2 a = *(const __half2*)&u.x;
        const __half2 c = *(const __half2*)&u.y;
        x0 = __low2float(a); x1v = __high2float(a);
        x2 = __low2float(c); x3 = __high2float(c);
    } else {
        const float4 v = ((const float4*)((const float*)Xv + row * HID))[t];
        x0 = v.x; x1v = v.y; x2 = v.z; x3 = v.w;
    }
    float s  = x0 + x1v + x2 + x3;
    float sq = x0*x0 + x1v*x1v + x2*x2 + x3*x3;

    #pragma unroll
    for (int o = 16; o > 0; o >>= 1) {
        s  += __shfl_xor_sync(0xffffffffu, s,  o);
        sq += __shfl_xor_sync(0xffffffffu, sq, o);
    }
    const int warp = t >> 5, lane = t & 31;
    if (lane == 0) { red[warp] = s; red[warp + 8] = sq; }
    __syncthreads();
    if (t < 32) {
        float ss = (lane < 8) ? red[lane]     : 0.f;
        float qq = (lane < 8) ? red[lane + 8] : 0.f;
        #pragma unroll
        for (int o = 4; o > 0; o >>= 1) {
            ss += __shfl_xor_sync(0xffffffffu, ss, o);
            qq += __shfl_xor_sync(0xffffffffu, qq, o);
        }
        if (lane == 0) { red[0] = ss; red[1] = qq; }
    }
    __syncthreads();

    const float mu   = red[0] * (1.f / HID);
    const float var  = red[1] * (1.f / HID) - mu * mu;
    const float rstd = rsqrtf(var + LN_EPS);

    const float4 gv = ((const float4*)g)[t];
    const float4 bv = ((const float4*)b)[t];
    __half2 a = __floats2half2_rn((x0  - mu) * rstd * gv.x + bv.x,
                                  (x1v - mu) * rstd * gv.y + bv.y);
    __half2 c = __floats2half2_rn((x2  - mu) * rstd * gv.z + bv.z,
                                  (x3  - mu) * rstd * gv.w + bv.w);
    uint2 u; u.x = *(uint32_t*)&a; u.y = *(uint32_t*)&c;
    *(uint2*)(Y + row * HID + t * 4) = u;
}

// ---------------------------------------------------------------------------
// Launch
// ---------------------------------------------------------------------------
extern "C" void kernel_launch(void* const* d_in, const int* in_sizes, int n_in,
                              void* d_out, int out_size)
{
    const float* x     = (const float*)d_in[0];
    const float* ln1_g = (const float*)d_in[1];
    const float* ln1_b = (const float*)d_in[2];
    const float* qkv_w = (const float*)d_in[3];
    const float* qkv_b = (const float*)d_in[4];
    const float* out_w = (const float*)d_in[5];
    const float* out_b = (const float*)d_in[6];
    const float* ln2_g = (const float*)d_in[7];
    const float* ln2_b = (const float*)d_in[8];
    const float* w1    = (const float*)d_in[9];
    const float* b1    = (const float*)d_in[10];
    const float* w2    = (const float*)d_in[11];
    const float* b2    = (const float*)d_in[12];
    float* out = (float*)d_out;

    __half *p_x1, *p_qkv, *p_h, *p_attn, *p_mid;
    __half *p_wqkv, *p_wout, *p_w1, *p_w2;
    cudaGetSymbolAddress((void**)&p_x1,   g_x1);
    cudaGetSymbolAddress((void**)&p_qkv,  g_qkv);
    cudaGetSymbolAddress((void**)&p_h,    g_h);
    cudaGetSymbolAddress((void**)&p_attn, g_attn);
    cudaGetSymbolAddress((void**)&p_mid,  g_mid);
    cudaGetSymbolAddress((void**)&p_wqkv, g_wqkv);
    cudaGetSymbolAddress((void**)&p_wout, g_wout);
    cudaGetSymbolAddress((void**)&p_w1,   g_w1);
    cudaGetSymbolAddress((void**)&p_w2,   g_w2);

    cudaFuncSetAttribute((const void*)hgemm2<0>,
                         cudaFuncAttributeMaxDynamicSharedMemorySize, HG2_SMEM);
    cudaFuncSetAttribute((const void*)hgemm2<1>,
                         cudaFuncAttributeMaxDynamicSharedMemorySize, HG2_SMEM);
    cudaFuncSetAttribute((const void*)hgemm2<2>,
                         cudaFuncAttributeMaxDynamicSharedMemorySize, HG2_SMEM);
    cudaFuncSetAttribute((const void*)hgemm2<3>,
                         cudaFuncAttributeMaxDynamicSharedMemorySize, HG2_SMEM);
    cudaFuncSetAttribute((const void*)attn_mma,
                         cudaFuncAttributeMaxDynamicSharedMemorySize, ATT_SMEM);

    // 0) weight conversions
    convw<<<(HID * 3 * HID / 4 + 255) / 256, 256>>>(qkv_w, p_wqkv, HID * 3 * HID);
    convw<<<(HID * HID / 4 + 255) / 256, 256>>>(out_w, p_wout, HID * HID);
    convw<<<(HID * INTER / 4 + 255) / 256, 256>>>(w1, p_w1, HID * INTER);
    convw<<<(INTER * HID / 4 + 255) / 256, 256>>>(w2, p_w2, INTER * HID);

    // 1) LN1: x (fp32) -> h (fp16)
    ln_kernel<0><<<NTOK, 256>>>(x, ln1_g, ln1_b, p_h);

    // 2) QKV: h @ wqkv + qkv_b -> qkv (fp16)
    hgemm2<0><<<dim3((3 * HID) / BN, NTOK / BM), 256, HG2_SMEM>>>(
        p_h, p_wqkv, qkv_b, nullptr, nullptr,
        nullptr, p_qkv, NTOK, 3 * HID, HID);

    // 3) attention: qkv -> attn
    attn_mma<<<dim3(SEQ / QT, NHEAD, BATCH), 256, ATT_SMEM>>>();

    // 4) x1 = x + attn @ wout + out_b  (fp16 out)
    hgemm2<1><<<dim3(HID / BN, NTOK / BM), 256, HG2_SMEM>>>(
        p_attn, p_wout, out_b, x, nullptr,
        nullptr, p_x1, NTOK, HID, HID);

    // 5) LN2: x1 (fp16) -> h (fp16)
    ln_kernel<1><<<NTOK, 256>>>(p_x1, ln2_g, ln2_b, p_h);

    // 6) mid = gelu(h @ w1 + b1)
    hgemm2<2><<<dim3(INTER / BN, NTOK / BM), 256, HG2_SMEM>>>(
        p_h, p_w1, b1, nullptr, nullptr,
        nullptr, p_mid, NTOK, INTER, HID);

    // 7) out = x1 + mid @ w2 + b2  (fp32 out)
    hgemm2<3><<<dim3(HID / BN, NTOK / BM), 256, HG2_SMEM>>>(
        p_mid, p_w2, b2, nullptr, p_x1,
        out, nullptr, NTOK, HID, INTER);
}

// round 17
// speedup vs baseline: 1.0771x; 1.0771x over previous
#include <cuda_runtime.h>
#include <cuda_fp16.h>
#include <math.h>
#include <stdint.h>

// ---------------------------------------------------------------------------
// Problem constants
// ---------------------------------------------------------------------------
#define HID   1024
#define NHEAD 16
#define HD    64
#define INTER 4096
#define BATCH 4
#define SEQ   2048
#define NTOK  (BATCH * SEQ)          // 8192
#define LN_EPS 1e-5f

// ---------------------------------------------------------------------------
// Scratch (static device globals; no runtime allocation)
// mma path single fp16; residual-1 fp16.
// ---------------------------------------------------------------------------
__device__ __half g_x1 [NTOK * HID];             // residual-1 (fp16)
__device__ __half g_qkv[NTOK * 3 * HID];         // QKV
__device__ __half g_h   [NTOK * HID];            // LN out
__device__ __half g_attn[NTOK * HID];            // attention out
__device__ __half g_mid [NTOK * INTER];          // GELU(MLP1)
__device__ __half g_wqkv[HID * 3 * HID];         // fp16 weights
__device__ __half g_wout[HID * HID];
__device__ __half g_w1  [HID * INTER];
__device__ __half g_w2  [INTER * HID];

// ---------------------------------------------------------------------------
// PTX helpers (sm_80-baseline features only)
// ---------------------------------------------------------------------------
__device__ __forceinline__ uint32_t smem_u32(const void* p) {
    uint32_t a;
    asm("{ .reg .u64 t; cvta.to.shared.u64 t, %1; cvt.u32.u64 %0, t; }"
        : "=r"(a) : "l"(p));
    return a;
}
__device__ __forceinline__ void ldsm4(uint32_t* r, uint32_t addr) {
    asm volatile("ldmatrix.sync.aligned.m8n8.x4.shared.b16 {%0,%1,%2,%3}, [%4];"
                 : "=r"(r[0]), "=r"(r[1]), "=r"(r[2]), "=r"(r[3]) : "r"(addr));
}
__device__ __forceinline__ void ldsm4t(uint32_t* r, uint32_t addr) {
    asm volatile("ldmatrix.sync.aligned.m8n8.x4.trans.shared.b16 {%0,%1,%2,%3}, [%4];"
                 : "=r"(r[0]), "=r"(r[1]), "=r"(r[2]), "=r"(r[3]) : "r"(addr));
}
__device__ __forceinline__ void mma_f16(float* c, const uint32_t* a,
                                        uint32_t b0, uint32_t b1) {
    asm volatile(
        "mma.sync.aligned.m16n8k16.row.col.f32.f16.f16.f32 "
        "{%0,%1,%2,%3}, {%4,%5,%6,%7}, {%8,%9}, {%0,%1,%2,%3};"
        : "+f"(c[0]), "+f"(c[1]), "+f"(c[2]), "+f"(c[3])
        : "r"(a[0]), "r"(a[1]), "r"(a[2]), "r"(a[3]), "r"(b0), "r"(b1));
}
__device__ __forceinline__ void cpasync16(uint32_t s, const void* g) {
    asm volatile("cp.async.cg.shared.global [%0], [%1], 16;" :: "r"(s), "l"(g));
}
#define CP_COMMIT() asm volatile("cp.async.commit_group;" ::: "memory")
#define CP_WAIT1()  asm volatile("cp.async.wait_group 1;"  ::: "memory")
#define CP_WAIT0()  asm volatile("cp.async.wait_group 0;"  ::: "memory")

__device__ __forceinline__ uint32_t swA(uint32_t off) { return off ^ ((off >> 2) & 0x30); }
__device__ __forceinline__ uint32_t swB(uint32_t off) { return off ^ ((off >> 4) & 0x70); }
__device__ __forceinline__ uint32_t sw128(uint32_t off) { return off ^ ((off >> 3) & 0x70); }

__device__ __forceinline__ uint32_t pack_h2(float x, float y) {
    __half2 h = __floats2half2_rn(x, y);
    return *(uint32_t*)&h;
}

// ---------------------------------------------------------------------------
// Weight fp32 -> fp16
// ---------------------------------------------------------------------------
__global__ __launch_bounds__(256) void convw(
    const float* __restrict__ w, __half* __restrict__ hi, int n)
{
    const int i = (blockIdx.x * 256 + threadIdx.x) * 4;
    if (i >= n) return;
    const float4 v = *(const float4*)(w + i);
    __half2 h01 = __floats2half2_rn(v.x, v.y);
    __half2 h23 = __floats2half2_rn(v.z, v.w);
    uint2 hv;
    hv.x = *(uint32_t*)&h01; hv.y = *(uint32_t*)&h23;
    *(uint2*)(hi + i) = hv;
}

// ---------------------------------------------------------------------------
// fp16 HMMA GEMM (R15 mainloop: BK=32, 3-stage, 16KB/stage = 48KB smem).
// EPI: 0 = +bias -> fp16; 1 = +bias + fp32 res -> fp16 (proj -> x1);
//      2 = +bias+GELU -> fp16; 3 = +bias + fp16 res -> fp32 (MLP2 -> out)
// ---------------------------------------------------------------------------
#define BM 128
#define BN 128
#define BK 32
#define ST_BYTES 16384
#define HG2_SMEM (3 * ST_BYTES)

template <int EPI>
__global__ __launch_bounds__(256, 2) void hgemm2(
    const __half* __restrict__ A, const __half* __restrict__ B,
    const float* __restrict__ bias, const float* __restrict__ resF,
    const __half* __restrict__ resH,
    float* __restrict__ Cf, __half* __restrict__ Ch,
    int M, int N, int K)
{
    extern __shared__ char smem[];
    const uint32_t sb = smem_u32(smem);
    const int tid  = threadIdx.x;
    const int lane = tid & 31;
    const int wid  = tid >> 5;
    const int m0   = blockIdx.y * BM;
    const int n0   = blockIdx.x * BN;

    const int ar  = tid >> 1;
    const int ae  = (tid & 1) * 16;
    const int bkr = tid >> 3;
    const int bne = (tid & 7) * 16;
    const uint32_t sA0 = swA(ar * 64 + ae * 2);
    const uint32_t sA1 = swA(ar * 64 + ae * 2 + 16);
    const uint32_t sB0 = swB(bkr * 256 + bne * 2);
    const uint32_t sB1 = swB(bkr * 256 + bne * 2 + 16);
    const size_t aoff = (size_t)(m0 + ar) * K + ae;

    auto PRE = [&](int c, int s) {
        const uint32_t st = sb + s * ST_BYTES;
        const __half* ap = A + aoff + c * BK;
        const size_t boff = (size_t)(c * BK + bkr) * N + n0 + bne;
        cpasync16(st + sA0, ap);
        cpasync16(st + sA1, ap + 8);
        cpasync16(st + 8192 + sB0, B + boff);
        cpasync16(st + 8192 + sB1, B + boff + 8);
    };

    const int wm  = (wid & 3) * 32;
    const int wn  = (wid >> 2) * 64;
    const int a_r = lane & 15;
    const int a_k = (lane >> 4) * 8;
    const int b_k = lane & 15;
    const int b_n = (lane >> 4) * 8;

    float acc[2][8][4];
    #pragma unroll
    for (int i = 0; i < 2; i++)
        #pragma unroll
        for (int j = 0; j < 8; j++)
            #pragma unroll
            for (int q = 0; q < 4; q++) acc[i][j][q] = 0.f;

    auto COMPUTE = [&](int s) {
        const uint32_t AS = sb + s * ST_BYTES;
        const uint32_t BS = AS + 8192;
        #pragma unroll
        for (int ks = 0; ks < 2; ks++) {
            uint32_t a_[2][4];
            #pragma unroll
            for (int mt = 0; mt < 2; mt++) {
                const uint32_t off = swA((wm + mt * 16 + a_r) * 64 + (ks * 16 + a_k) * 2);
                ldsm4(a_[mt], AS + off);
            }
            #pragma unroll
            for (int ng = 0; ng < 4; ng++) {
                uint32_t bh[4];
                const uint32_t off = swB((ks * 16 + b_k) * 256 + (wn + ng * 16 + b_n) * 2);
                ldsm4t(bh, BS + off);
                #pragma unroll
                for (int mt = 0; mt < 2; mt++) {
                    #pragma unroll
                    for (int hf = 0; hf < 2; hf++)
                        mma_f16(acc[mt][ng * 2 + hf], a_[mt],
                                bh[hf * 2], bh[hf * 2 + 1]);
                }
            }
        }
    };

    PRE(0, 0); CP_COMMIT();
    PRE(1, 1); CP_COMMIT();
    const int NC = K / BK;
    #pragma unroll 1
    for (int c = 0; c < NC; c++) {
        const int s = c - (c / 3) * 3;
        CP_WAIT1();
        __syncthreads();
        COMPUTE(s);
        if (c + 2 < NC) {
            const int s2 = (c + 2) - ((c + 2) / 3) * 3;
            PRE(c + 2, s2);
        }
        CP_COMMIT();
    }

    #pragma unroll
    for (int mt = 0; mt < 2; mt++) {
        #pragma unroll
        for (int nt = 0; nt < 8; nt++) {
            const int r0 = m0 + wm + mt * 16 + (lane >> 2);
            const int cc = n0 + wn + nt * 8 + (lane & 3) * 2;
            const float bx = bias[cc], by = bias[cc + 1];
            #pragma unroll
            for (int half = 0; half < 2; half++) {
                const int r = r0 + half * 8;
                float vx = acc[mt][nt][half * 2 + 0] + bx;
                float vy = acc[mt][nt][half * 2 + 1] + by;
                if (EPI == 2) {
                    float t = tanhf(0.7978845608028654f * (vx + 0.044715f * vx * vx * vx));
                    vx = 0.5f * vx * (1.0f + t);
                    t = tanhf(0.7978845608028654f * (vy + 0.044715f * vy * vy * vy));
                    vy = 0.5f * vy * (1.0f + t);
                }
                if (EPI == 1) {
                    const float2 rv = *(const float2*)(resF + (size_t)r * N + cc);
                    vx += rv.x; vy += rv.y;
                }
                if (EPI == 3) {
                    const __half2 rh = *(const __half2*)(resH + (size_t)r * N + cc);
                    vx += __low2float(rh); vy += __high2float(rh);
                    float2 w; w.x = vx; w.y = vy;
                    *(float2*)(Cf + (size_t)r * N + cc) = w;
                } else {
                    *(__half2*)(Ch + (size_t)r * N + cc) = __floats2half2_rn(vx, vy);
                }
            }
        }
    }
}

// ---------------------------------------------------------------------------
// Tensor-core flash attention (R15, unchanged): single fp16, 1-term.
// Smem: Q 16K | 2 x (K 8K + V 8K) = 48KB. 2 CTA/SM.
// ---------------------------------------------------------------------------
#define QT 128
#define KT 64
#define ATT_SMEM (16384 + 2 * 16384)

__global__ __launch_bounds__(256, 2) void attn_mma()
{
    extern __shared__ char smem[];
    const uint32_t sb = smem_u32(smem);
    const int tid  = threadIdx.x;
    const int lane = tid & 31;
    const int wid  = tid >> 5;
    const int h    = blockIdx.y;
    const int bb   = blockIdx.z;
    const int q0   = blockIdx.x * QT;

    {
        const int qr  = tid >> 1;
        const int qc0 = (tid & 1) * 32;
        const size_t gq = (size_t)(bb * SEQ + q0 + qr) * 3072 + h * 64 + qc0;
        #pragma unroll
        for (int i = 0; i < 4; i++) {
            const uint32_t so = sw128(qr * 128 + (qc0 + i * 8) * 2);
            cpasync16(sb + so, g_qkv + gq + i * 8);
        }
    }

    const int kr = tid >> 2;
    const int kc = (tid & 3) * 16;
    auto PRE = [&](int c, int s) {
        const uint32_t st = sb + 16384 + s * 16384;
        const size_t base = (size_t)(bb * SEQ + c * KT + kr) * 3072 + h * 64 + kc;
        const uint32_t so0 = sw128(kr * 128 + kc * 2);
        const uint32_t so1 = so0 ^ 16;
        cpasync16(st + so0,         g_qkv + base + 1024);
        cpasync16(st + so1,         g_qkv + base + 1024 + 8);
        cpasync16(st + 8192 + so0,  g_qkv + base + 2048);
        cpasync16(st + 8192 + so1,  g_qkv + base + 2048 + 8);
    };

    PRE(0, 0); CP_COMMIT();
    PRE(1, 1); CP_COMMIT();
    CP_WAIT1();
    __syncthreads();

    const int wm = wid * 16;

    float oacc[8][4];
    #pragma unroll
    for (int j = 0; j < 8; j++)
        #pragma unroll
        for (int q = 0; q < 4; q++) oacc[j][q] = 0.f;
    float m0 = -1e30f, m1 = -1e30f, l0 = 0.f, l1 = 0.f;

    const int k_rowadd = ((lane >> 4) & 1) * 8;
    const int k_koff   = ((lane >> 3) & 1) * 8;
    const int k_r8     = lane & 7;

    const int NCH = SEQ / KT;
    #pragma unroll 1
    for (int c = 0; c < NCH; c++) {
        const int s = c & 1;
        const uint32_t st  = sb + 16384 + s * 16384;
        const uint32_t Kb = st, Vb = st + 8192;

        float sacc[8][4];
        #pragma unroll
        for (int j = 0; j < 8; j++)
            #pragma unroll
            for (int q = 0; q < 4; q++) sacc[j][q] = 0.f;

        #pragma unroll
        for (int ks = 0; ks < 4; ks++) {
            uint32_t qf[4];
            const uint32_t qoff =
                sw128((wm + (lane & 15)) * 128 + (ks * 16 + (lane >> 4) * 8) * 2);
            ldsm4(qf, sb + qoff);
            #pragma unroll
            for (int j = 0; j < 4; j++) {
                const uint32_t off = sw128((j * 16 + k_r8 + k_rowadd) * 128 +
                                           (ks * 16 + k_koff) * 2);
                uint32_t kb[4];
                ldsm4(kb, Kb + off);
                #pragma unroll
                for (int t2 = 0; t2 < 2; t2++)
                    mma_f16(sacc[j * 2 + t2], qf, kb[t2 * 2], kb[t2 * 2 + 1]);
            }
        }

        float vm0 = -1e30f, vm1 = -1e30f;
        #pragma unroll
        for (int j = 0; j < 8; j++) {
            vm0 = fmaxf(vm0, fmaxf(sacc[j][0], sacc[j][1]));
            vm1 = fmaxf(vm1, fmaxf(sacc[j][2], sacc[j][3]));
        }
        vm0 = fmaxf(vm0, __shfl_xor_sync(0xffffffffu, vm0, 1));
        vm0 = fmaxf(vm0, __shfl_xor_sync(0xffffffffu, vm0, 2));
        vm1 = fmaxf(vm1, __shfl_xor_sync(0xffffffffu, vm1, 1));
        vm1 = fmaxf(vm1, __shfl_xor_sync(0xffffffffu, vm1, 2));
        vm0 *= 0.125f; vm1 *= 0.125f;

        const float mn0 = fmaxf(m0, vm0), mn1 = fmaxf(m1, vm1);
        const float c0 = __expf(m0 - mn0), c1 = __expf(m1 - mn1);
        m0 = mn0; m1 = mn1;
        l0 *= c0;  l1 *= c1;
        #pragma unroll
        for (int j = 0; j < 8; j++) {
            oacc[j][0] *= c0; oacc[j][1] *= c0;
            oacc[j][2] *= c1; oacc[j][3] *= c1;
        }
        #pragma unroll
        for (int j = 0; j < 8; j++) {
            sacc[j][0] = __expf(fmaf(sacc[j][0], 0.125f, -mn0));
            sacc[j][1] = __expf(fmaf(sacc[j][1], 0.125f, -mn0));
            sacc[j][2] = __expf(fmaf(sacc[j][2], 0.125f, -mn1));
            sacc[j][3] = __expf(fmaf(sacc[j][3], 0.125f, -mn1));
            l0 += sacc[j][0] + sacc[j][1];
            l1 += sacc[j][2] + sacc[j][3];
        }

        #pragma unroll
        for (int kk = 0; kk < 4; kk++) {
            const float* p0 = sacc[kk * 2];
            const float* p1 = sacc[kk * 2 + 1];
            uint32_t pa[4];
            pa[0] = pack_h2(p0[0], p0[1]);
            pa[1] = pack_h2(p0[2], p0[3]);
            pa[2] = pack_h2(p1[0], p1[1]);
            pa[3] = pack_h2(p1[2], p1[3]);
            #pragma unroll
            for (int j = 0; j < 4; j++) {
                const uint32_t off = sw128((kk * 16 + (lane & 15)) * 128 +
                                           (j * 16 + (lane >> 4) * 8) * 2);
                uint32_t vb[4];
                ldsm4t(vb, Vb + off);
                #pragma unroll
                for (int t2 = 0; t2 < 2; t2++)
                    mma_f16(oacc[j * 2 + t2], pa, vb[t2 * 2], vb[t2 * 2 + 1]);
            }
        }

        if (c + 1 < NCH) {
            __syncthreads();
            if (c + 2 < NCH) {
                PRE(c + 2, s);
                CP_COMMIT();
                CP_WAIT1();
            } else {
                CP_WAIT0();
            }
            __syncthreads();
        }
    }

    l0 += __shfl_xor_sync(0xffffffffu, l0, 1);
    l0 += __shfl_xor_sync(0xffffffffu, l0, 2);
    l1 += __shfl_xor_sync(0xffffffffu, l1, 1);
    l1 += __shfl_xor_sync(0xffffffffu, l1, 2);
    const float i0 = 1.f / l0, i1 = 1.f / l1;

    const int r0g = bb * SEQ + q0 + wm + (lane >> 2);
    const int cb  = h * 64 + (lane & 3) * 2;
    #pragma unroll
    for (int j = 0; j < 8; j++) {
        *(__half2*)(g_attn + (size_t)r0g * HID + cb + j * 8) =
            __floats2half2_rn(oacc[j][0] * i0, oacc[j][1] * i0);
        *(__half2*)(g_attn + (size_t)(r0g + 8) * HID + cb + j * 8) =
            __floats2half2_rn(oacc[j][2] * i1, oacc[j][3] * i1);
    }
}

// ---------------------------------------------------------------------------
// LayerNorm: FP16IN=0 -> fp32 input; FP16IN=1 -> fp16 input. fp16 out.
// ---------------------------------------------------------------------------
template <int FP16IN>
__global__ __launch_bounds__(256) void ln_kernel(
    const void* __restrict__ Xv, const float* __restrict__ g,
    const float* __restrict__ b, __half* __restrict__ Y)
{
    __shared__ float red[16];
    const long row = blockIdx.x;
    const int  t   = threadIdx.x;

    float x0, x1v, x2, x3;
    if (FP16IN) {
        const uint2 u = ((const uint2*)((const __half*)Xv + row * HID))[t];
        const __half2 a = *(const __half2*)&u.x;
        const __half2 c = *(const __half2*)&u.y;
        x0 = __low2float(a); x1v = __high2float(a);
        x2 = __low2float(c); x3 = __high2float(c);
    } else {
        const float4 v = ((const float4*)((const float*)Xv + row * HID))[t];
        x0 = v.x; x1v = v.y; x2 = v.z; x3 = v.w;
    }
    float s  = x0 + x1v + x2 + x3;
    float sq = x0*x0 + x1v*x1v + x2*x2 + x3*x3;

    #pragma unroll
    for (int o = 16; o > 0; o >>= 1) {
        s  += __shfl_xor_sync(0xffffffffu, s,  o);
        sq += __shfl_xor_sync(0xffffffffu, sq, o);
    }
    const int warp = t >> 5, lane = t & 31;
    if (lane == 0) { red[warp] = s; red[warp + 8] = sq; }
    __syncthreads();
    if (t < 32) {
        float ss = (lane < 8) ? red[lane]     : 0.f;
        float qq = (lane < 8) ? red[lane + 8] : 0.f;
        #pragma unroll
        for (int o = 4; o > 0; o >>= 1) {
            ss += __shfl_xor_sync(0xffffffffu, ss, o);
            qq += __shfl_xor_sync(0xffffffffu, qq, o);
        }
        if (lane == 0) { red[0] = ss; red[1] = qq; }
    }
    __syncthreads();

    const float mu   = red[0] * (1.f / HID);
    const float var  = red[1] * (1.f / HID) - mu * mu;
    const float rstd = rsqrtf(var + LN_EPS);

    const float4 gv = ((const float4*)g)[t];
    const float4 bv = ((const float4*)b)[t];
    __half2 a = __floats2half2_rn((x0  - mu) * rstd * gv.x + bv.x,
                                  (x1v - mu) * rstd * gv.y + bv.y);
    __half2 c = __floats2half2_rn((x2  - mu) * rstd * gv.z + bv.z,
                                  (x3  - mu) * rstd * gv.w + bv.w);
    uint2 u; u.x = *(uint32_t*)&a; u.y = *(uint32_t*)&c;
    *(uint2*)(Y + row * HID + t * 4) = u;
}

// ---------------------------------------------------------------------------
// Launch
// ---------------------------------------------------------------------------
extern "C" void kernel_launch(void* const* d_in, const int* in_sizes, int n_in,
                              void* d_out, int out_size)
{
    const float* x     = (const float*)d_in[0];
    const float* ln1_g = (const float*)d_in[1];
    const float* ln1_b = (const float*)d_in[2];
    const float* qkv_w = (const float*)d_in[3];
    const float* qkv_b = (const float*)d_in[4];
    const float* out_w = (const float*)d_in[5];
    const float* out_b = (const float*)d_in[6];
    const float* ln2_g = (const float*)d_in[7];
    const float* ln2_b = (const float*)d_in[8];
    const float* w1    = (const float*)d_in[9];
    const float* b1    = (const float*)d_in[10];
    const float* w2    = (const float*)d_in[11];
    const float* b2    = (const float*)d_in[12];
    float* out = (float*)d_out;

    __half *p_x1, *p_qkv, *p_h, *p_attn, *p_mid;
    __half *p_wqkv, *p_wout, *p_w1, *p_w2;
    cudaGetSymbolAddress((void**)&p_x1,   g_x1);
    cudaGetSymbolAddress((void**)&p_qkv,  g_qkv);
    cudaGetSymbolAddress((void**)&p_h,    g_h);
    cudaGetSymbolAddress((void**)&p_attn, g_attn);
    cudaGetSymbolAddress((void**)&p_mid,  g_mid);
    cudaGetSymbolAddress((void**)&p_wqkv, g_wqkv);
    cudaGetSymbolAddress((void**)&p_wout, g_wout);
    cudaGetSymbolAddress((void**)&p_w1,   g_w1);
    cudaGetSymbolAddress((void**)&p_w2,   g_w2);

    cudaFuncSetAttribute((const void*)hgemm2<0>,
                         cudaFuncAttributeMaxDynamicSharedMemorySize, HG2_SMEM);
    cudaFuncSetAttribute((const void*)hgemm2<1>,
                         cudaFuncAttributeMaxDynamicSharedMemorySize, HG2_SMEM);
    cudaFuncSetAttribute((const void*)hgemm2<2>,
                         cudaFuncAttributeMaxDynamicSharedMemorySize, HG2_SMEM);
    cudaFuncSetAttribute((const void*)hgemm2<3>,
                         cudaFuncAttributeMaxDynamicSharedMemorySize, HG2_SMEM);
    cudaFuncSetAttribute((const void*)attn_mma,
                         cudaFuncAttributeMaxDynamicSharedMemorySize, ATT_SMEM);

    // 0) weight conversions
    convw<<<(HID * 3 * HID / 4 + 255) / 256, 256>>>(qkv_w, p_wqkv, HID * 3 * HID);
    convw<<<(HID * HID / 4 + 255) / 256, 256>>>(out_w, p_wout, HID * HID);
    convw<<<(HID * INTER / 4 + 255) / 256, 256>>>(w1, p_w1, HID * INTER);
    convw<<<(INTER * HID / 4 + 255) / 256, 256>>>(w2, p_w2, INTER * HID);

    // 1) LN1: x (fp32) -> h (fp16)
    ln_kernel<0><<<NTOK, 256>>>(x, ln1_g, ln1_b, p_h);

    // 2) QKV: h @ wqkv + qkv_b -> qkv (fp16)
    hgemm2<0><<<dim3((3 * HID) / BN, NTOK / BM), 256, HG2_SMEM>>>(
        p_h, p_wqkv, qkv_b, nullptr, nullptr,
        nullptr, p_qkv, NTOK, 3 * HID, HID);

    // 3) attention: qkv -> attn
    attn_mma<<<dim3(SEQ / QT, NHEAD, BATCH), 256, ATT_SMEM>>>();

    // 4) x1 = x + attn @ wout + out_b  (fp16 out)
    hgemm2<1><<<dim3(HID / BN, NTOK / BM), 256, HG2_SMEM>>>(
        p_attn, p_wout, out_b, x, nullptr,
        nullptr, p_x1, NTOK, HID, HID);

    // 5) LN2: x1 (fp16) -> h (fp16)
    ln_kernel<1><<<NTOK, 256>>>(p_x1, ln2_g, ln2_b, p_h);

    // 6) mid = gelu(h @ w1 + b1)
    hgemm2<2><<<dim3(INTER / BN, NTOK / BM), 256, HG2_SMEM>>>(
        p_h, p_w1, b1, nullptr, nullptr,
        nullptr, p_mid, NTOK, INTER, HID);

    // 7) out = x1 + mid @ w2 + b2  (fp32 out)
    hgemm2<3><<<dim3(HID / BN, NTOK / BM), 256, HG2_SMEM>>>(
        p_mid, p_w2, b2, nullptr, p_x1,
        out, nullptr, NTOK, HID, INTER);
}